// round 5
// baseline (speedup 1.0000x reference)
#include <cuda_runtime.h>
#include <math.h>

// ---------------------------------------------------------------------------
// BayesianLinear: out = x @ (mu + exp(ls)*eps)^T + bias ;  unc = sqrt(x^2 @ (exp(ls)^2)^T + bsig^2)
// B=4096, IN=2048, OUT=2048, fp32. Output tuple (output, uncertainty) concatenated in d_out.
// ---------------------------------------------------------------------------

#define B_DIM   4096
#define IN_DIM  2048
#define OUT_DIM 2048

#define BM 128
#define BN 64
#define BK 32

// Scratch for the materialized sampled weight and sigma^2 (prep kernel fills these).
static __device__ float g_w [OUT_DIM * IN_DIM];
static __device__ float g_s2[OUT_DIM * IN_DIM];

// ---- packed f32x2 helpers (sm_100+ PTX) -----------------------------------
__device__ __forceinline__ unsigned long long ffma2(unsigned long long a,
                                                    unsigned long long b,
                                                    unsigned long long c) {
    unsigned long long d;
    asm("fma.rn.f32x2 %0, %1, %2, %3;" : "=l"(d) : "l"(a), "l"(b), "l"(c));
    return d;
}
__device__ __forceinline__ unsigned long long fmul2(unsigned long long a,
                                                    unsigned long long b) {
    unsigned long long d;
    asm("mul.rn.f32x2 %0, %1, %2;" : "=l"(d) : "l"(a), "l"(b));
    return d;
}
__device__ __forceinline__ unsigned long long bcast2(float v) {
    unsigned long long d;
    asm("mov.b64 %0, {%1, %1};" : "=l"(d) : "f"(v));
    return d;
}

// ---------------------------------------------------------------------------
// Prep: w = mu + exp(ls)*eps ; s2 = exp(ls)^2   (4M elements, vectorized)
// ---------------------------------------------------------------------------
__global__ void __launch_bounds__(256) bl_prep(const float4* __restrict__ mu,
                                               const float4* __restrict__ ls,
                                               const float4* __restrict__ ep) {
    int i = blockIdx.x * 256 + threadIdx.x;   // indexes float4, total (2048*2048)/4
    float4 m = mu[i];
    float4 l = ls[i];
    float4 e = ep[i];
    float sx = __expf(l.x), sy = __expf(l.y), sz = __expf(l.z), sw = __expf(l.w);
    float4 w  = make_float4(m.x + sx * e.x, m.y + sy * e.y,
                            m.z + sz * e.z, m.w + sw * e.w);
    float4 s2 = make_float4(sx * sx, sy * sy, sz * sz, sw * sw);
    reinterpret_cast<float4*>(g_w )[i] = w;
    reinterpret_cast<float4*>(g_s2)[i] = s2;
}

// ---------------------------------------------------------------------------
// Main fused double-GEMM.
// Block tile: BM x BN, K-chunk BK. 256 threads, each computes 8(m) x 4(n)
// results for BOTH output and variance, as f32x2 pairs along m.
// ---------------------------------------------------------------------------
__global__ void __launch_bounds__(256, 2) bl_main(
    const float* __restrict__ x,
    const float* __restrict__ bias_mu,
    const float* __restrict__ bias_ls,
    const float* __restrict__ eps_b,
    float* __restrict__ out,
    float* __restrict__ unc)
{
    __shared__ __align__(16) float xs[BK][BM + 4];   // [32][132] transposed x tile
    __shared__ __align__(16) float ws[BK][BN + 4];   // [32][68]  transposed w tile
    __shared__ __align__(16) float ss[BK][BN + 4];   // [32][68]  transposed s2 tile

    const int tid = threadIdx.x;
    const int tx  = tid & 15;       // n group: 16 x 4 cols = 64
    const int ty  = tid >> 4;       // m group: 16 x 8 rows = 128
    const int m0  = ty * 8;
    const int n0  = tx * 4;
    const int bm  = blockIdx.y * BM;
    const int bn  = blockIdx.x * BN;

    const float* __restrict__ gw = g_w;
    const float* __restrict__ gs = g_s2;

    unsigned long long o_acc[4][4];   // [m-pair][n]
    unsigned long long v_acc[4][4];
#pragma unroll
    for (int i = 0; i < 4; ++i)
#pragma unroll
        for (int j = 0; j < 4; ++j) { o_acc[i][j] = 0ULL; v_acc[i][j] = 0ULL; }

    for (int kt = 0; kt < IN_DIM; kt += BK) {
        // ---- stage x tile: 128 rows x 32 k  (1024 float4 chunks) ----------
#pragma unroll
        for (int it = 0; it < 4; ++it) {
            int c  = tid + it * 256;
            int m  = c >> 3;                 // row within tile
            int kc = c & 7;                  // float4 chunk within row
            float4 v = *reinterpret_cast<const float4*>(
                &x[(size_t)(bm + m) * IN_DIM + kt + kc * 4]);
            xs[kc * 4 + 0][m] = v.x;
            xs[kc * 4 + 1][m] = v.y;
            xs[kc * 4 + 2][m] = v.z;
            xs[kc * 4 + 3][m] = v.w;
        }
        // ---- stage w + s2 tiles: 64 rows x 32 k (512 chunks each) ---------
#pragma unroll
        for (int it = 0; it < 2; ++it) {
            int c  = tid + it * 256;
            int n  = c >> 3;
            int kc = c & 7;
            size_t gidx = (size_t)(bn + n) * IN_DIM + kt + kc * 4;
            float4 wv = *reinterpret_cast<const float4*>(&gw[gidx]);
            float4 sv = *reinterpret_cast<const float4*>(&gs[gidx]);
            ws[kc * 4 + 0][n] = wv.x;
            ws[kc * 4 + 1][n] = wv.y;
            ws[kc * 4 + 2][n] = wv.z;
            ws[kc * 4 + 3][n] = wv.w;
            ss[kc * 4 + 0][n] = sv.x;
            ss[kc * 4 + 1][n] = sv.y;
            ss[kc * 4 + 2][n] = sv.z;
            ss[kc * 4 + 3][n] = sv.w;
        }
        __syncthreads();

        // ---- compute ------------------------------------------------------
#pragma unroll
        for (int k = 0; k < BK; ++k) {
            // A fragment: 8 m values = 4 f32x2 pairs, straight from LDS.128
            ulonglong2 a01 = *reinterpret_cast<const ulonglong2*>(&xs[k][m0]);
            ulonglong2 a23 = *reinterpret_cast<const ulonglong2*>(&xs[k][m0 + 4]);
            unsigned long long ap[4] = { a01.x, a01.y, a23.x, a23.y };

            float4 wv = *reinterpret_cast<const float4*>(&ws[k][n0]);
            float4 sv = *reinterpret_cast<const float4*>(&ss[k][n0]);
            unsigned long long wp[4] = { bcast2(wv.x), bcast2(wv.y),
                                         bcast2(wv.z), bcast2(wv.w) };
            unsigned long long sp[4] = { bcast2(sv.x), bcast2(sv.y),
                                         bcast2(sv.z), bcast2(sv.w) };

            unsigned long long a2p[4];
#pragma unroll
            for (int i = 0; i < 4; ++i) a2p[i] = fmul2(ap[i], ap[i]);

#pragma unroll
            for (int i = 0; i < 4; ++i)
#pragma unroll
                for (int j = 0; j < 4; ++j) {
                    o_acc[i][j] = ffma2(ap[i],  wp[j], o_acc[i][j]);
                    v_acc[i][j] = ffma2(a2p[i], sp[j], v_acc[i][j]);
                }
        }
        __syncthreads();
    }

    // ---- epilogue: bias, sqrt, stores -------------------------------------
#pragma unroll
    for (int j = 0; j < 4; ++j) {
        int ng = bn + n0 + j;
        float bsig = __expf(bias_ls[ng]);
        float bias = bias_mu[ng] + bsig * eps_b[ng];
        float bs2  = bsig * bsig;
#pragma unroll
        for (int i = 0; i < 4; ++i) {
            union { unsigned long long u; float2 f; } o, v;
            o.u = o_acc[i][j];
            v.u = v_acc[i][j];
            size_t r0 = (size_t)(bm + m0 + 2 * i) * OUT_DIM + ng;
            out[r0]           = o.f.x + bias;
            out[r0 + OUT_DIM] = o.f.y + bias;
            unc[r0]           = sqrtf(v.f.x + bs2);
            unc[r0 + OUT_DIM] = sqrtf(v.f.y + bs2);
        }
    }
}

// ---------------------------------------------------------------------------
// kernel_launch — graph-capturable, allocation-free.
// Input order per metadata: x, weight_mu, weight_log_sigma, bias_mu,
//                           bias_log_sigma, eps_w, eps_b
// Output: [output (4096x2048) | uncertainty (4096x2048)] fp32
// ---------------------------------------------------------------------------
extern "C" void kernel_launch(void* const* d_in, const int* in_sizes, int n_in,
                              void* d_out, int out_size)
{
    const float* x   = (const float*)d_in[0];
    const float* wmu = (const float*)d_in[1];
    const float* wls = (const float*)d_in[2];
    const float* bmu = (const float*)d_in[3];
    const float* bls = (const float*)d_in[4];
    const float* ew  = (const float*)d_in[5];
    const float* eb  = (const float*)d_in[6];

    float* out = (float*)d_out;
    float* unc = out + (size_t)B_DIM * OUT_DIM;

    // 1) materialize sampled weight + sigma^2 once per launch
    int n4 = (OUT_DIM * IN_DIM) / 4;                 // 1,048,576 float4
    bl_prep<<<n4 / 256, 256>>>((const float4*)wmu, (const float4*)wls,
                               (const float4*)ew);

    // 2) fused double-GEMM
    dim3 grid(OUT_DIM / BN, B_DIM / BM);             // (32, 32)
    bl_main<<<grid, 256>>>(x, bmu, bls, eb, out, unc);

    (void)in_sizes; (void)n_in; (void)out_size;
}

// round 8
// speedup vs baseline: 1.9022x; 1.9022x over previous
#include <cuda_runtime.h>
#include <cuda_bf16.h>
#include <cstdint>
#include <math.h>

// ---------------------------------------------------------------------------
// BayesianLinear via sm80-path bf16-split HMMA (mma.sync.m16n8k16).
//   out = x @ (mu + exp(ls)*eps)^T + bias
//   unc = sqrt(x^2 @ (exp(ls)^2)^T + bias_sigma^2)
// fp32 operands split hi/lo bf16: out = xh*wh + xh*wl + xl*wh (fp32 acc),
// var = x2*(s2h + s2l). tcgen05 is unavailable (harness PTX target = sm_103,
// no 'a' suffix) -- mma.sync/ldmatrix/cp.async are plain sm_80 features.
// ---------------------------------------------------------------------------

#define B_DIM   4096
#define IN_DIM  2048
#define OUT_DIM 2048

#define BM 128
#define BN 64
#define BK 32
#define NCHUNK (IN_DIM / BK)      // 64

// Stage layout (bytes): A tiles 128x32 bf16 = 8192 each; B tiles 64x32 = 4096.
#define ST_XH   0
#define ST_XL   8192
#define ST_X2   16384
#define ST_WH   24576
#define ST_WL   28672
#define ST_S2H  32768
#define ST_S2L  36864
#define STAGE_BYTES 40960
#define NSTAGE  3
#define SMEM_DYN (NSTAGE * STAGE_BYTES)   // 122880

// ---- scratch (allocation-free: __device__ globals) ------------------------
static __device__ __align__(16) __nv_bfloat16 g_xh [B_DIM  * IN_DIM];
static __device__ __align__(16) __nv_bfloat16 g_xl [B_DIM  * IN_DIM];
static __device__ __align__(16) __nv_bfloat16 g_x2 [B_DIM  * IN_DIM];
static __device__ __align__(16) __nv_bfloat16 g_wh [OUT_DIM * IN_DIM];
static __device__ __align__(16) __nv_bfloat16 g_wl [OUT_DIM * IN_DIM];
static __device__ __align__(16) __nv_bfloat16 g_s2h[OUT_DIM * IN_DIM];
static __device__ __align__(16) __nv_bfloat16 g_s2l[OUT_DIM * IN_DIM];

// ---- PTX helpers ----------------------------------------------------------
__device__ __forceinline__ uint32_t smem_u32(const void* p) {
    uint32_t a;
    asm("{ .reg .u64 t; cvta.to.shared.u64 t, %1; cvt.u32.u64 %0, t; }"
        : "=r"(a) : "l"(p));
    return a;
}
__device__ __forceinline__ void cp16(uint32_t dst, const void* src) {
    asm volatile("cp.async.cg.shared.global [%0], [%1], 16;"
                 :: "r"(dst), "l"(__cvta_generic_to_global(src)) : "memory");
}
#define CP_COMMIT() asm volatile("cp.async.commit_group;" ::: "memory")
#define CP_WAIT2()  asm volatile("cp.async.wait_group 2;" ::: "memory")

__device__ __forceinline__ void ldsm_x4(uint32_t* r, uint32_t addr) {
    asm volatile("ldmatrix.sync.aligned.m8n8.x4.shared.b16 {%0,%1,%2,%3}, [%4];"
                 : "=r"(r[0]), "=r"(r[1]), "=r"(r[2]), "=r"(r[3]) : "r"(addr));
}
__device__ __forceinline__ void mma_bf16(float* d, const uint32_t* a,
                                         const uint32_t* b) {
    asm volatile(
        "mma.sync.aligned.m16n8k16.row.col.f32.bf16.bf16.f32 "
        "{%0,%1,%2,%3}, {%4,%5,%6,%7}, {%8,%9}, {%0,%1,%2,%3};"
        : "+f"(d[0]), "+f"(d[1]), "+f"(d[2]), "+f"(d[3])
        : "r"(a[0]), "r"(a[1]), "r"(a[2]), "r"(a[3]), "r"(b[0]), "r"(b[1]));
}
__device__ __forceinline__ uint32_t pack2(__nv_bfloat16 a, __nv_bfloat16 b) {
    __nv_bfloat162 t(a, b);
    return *reinterpret_cast<uint32_t*>(&t);
}
// swizzled byte offset within a tile (rows of 64B = 4 x 16B chunks)
__device__ __forceinline__ uint32_t swz(int row, int c) {
    return (uint32_t)(row * 64 + ((c ^ ((row >> 1) & 3)) << 4));
}

// ---------------------------------------------------------------------------
// Prep kernels: fp32 -> bf16 hi/lo splits + squared terms.
// ---------------------------------------------------------------------------
__global__ void __launch_bounds__(256) prep_w(const float4* __restrict__ mu,
                                              const float4* __restrict__ ls,
                                              const float4* __restrict__ ep) {
    int i = blockIdx.x * 256 + threadIdx.x;
    float4 m = mu[i], l = ls[i], e = ep[i];
    float s0 = __expf(l.x), s1 = __expf(l.y), s2 = __expf(l.z), s3 = __expf(l.w);
    float w0 = m.x + s0 * e.x, w1 = m.y + s1 * e.y;
    float w2 = m.z + s2 * e.z, w3 = m.w + s3 * e.w;

    __nv_bfloat16 h0 = __float2bfloat16(w0), h1 = __float2bfloat16(w1);
    __nv_bfloat16 h2 = __float2bfloat16(w2), h3 = __float2bfloat16(w3);
    __nv_bfloat16 l0 = __float2bfloat16(w0 - __bfloat162float(h0));
    __nv_bfloat16 l1 = __float2bfloat16(w1 - __bfloat162float(h1));
    __nv_bfloat16 l2 = __float2bfloat16(w2 - __bfloat162float(h2));
    __nv_bfloat16 l3 = __float2bfloat16(w3 - __bfloat162float(h3));

    float q0 = s0 * s0, q1 = s1 * s1, q2 = s2 * s2, q3 = s3 * s3;
    __nv_bfloat16 a0 = __float2bfloat16(q0), a1 = __float2bfloat16(q1);
    __nv_bfloat16 a2 = __float2bfloat16(q2), a3 = __float2bfloat16(q3);
    __nv_bfloat16 b0 = __float2bfloat16(q0 - __bfloat162float(a0));
    __nv_bfloat16 b1 = __float2bfloat16(q1 - __bfloat162float(a1));
    __nv_bfloat16 b2 = __float2bfloat16(q2 - __bfloat162float(a2));
    __nv_bfloat16 b3 = __float2bfloat16(q3 - __bfloat162float(a3));

    reinterpret_cast<uint2*>(g_wh )[i] = make_uint2(pack2(h0, h1), pack2(h2, h3));
    reinterpret_cast<uint2*>(g_wl )[i] = make_uint2(pack2(l0, l1), pack2(l2, l3));
    reinterpret_cast<uint2*>(g_s2h)[i] = make_uint2(pack2(a0, a1), pack2(a2, a3));
    reinterpret_cast<uint2*>(g_s2l)[i] = make_uint2(pack2(b0, b1), pack2(b2, b3));
}

__global__ void __launch_bounds__(256) prep_x(const float4* __restrict__ x) {
    int i = blockIdx.x * 256 + threadIdx.x;
    float4 v = x[i];
    __nv_bfloat16 h0 = __float2bfloat16(v.x), h1 = __float2bfloat16(v.y);
    __nv_bfloat16 h2 = __float2bfloat16(v.z), h3 = __float2bfloat16(v.w);
    __nv_bfloat16 l0 = __float2bfloat16(v.x - __bfloat162float(h0));
    __nv_bfloat16 l1 = __float2bfloat16(v.y - __bfloat162float(h1));
    __nv_bfloat16 l2 = __float2bfloat16(v.z - __bfloat162float(h2));
    __nv_bfloat16 l3 = __float2bfloat16(v.w - __bfloat162float(h3));
    __nv_bfloat16 q0 = __float2bfloat16(v.x * v.x);
    __nv_bfloat16 q1 = __float2bfloat16(v.y * v.y);
    __nv_bfloat16 q2 = __float2bfloat16(v.z * v.z);
    __nv_bfloat16 q3 = __float2bfloat16(v.w * v.w);

    reinterpret_cast<uint2*>(g_xh)[i] = make_uint2(pack2(h0, h1), pack2(h2, h3));
    reinterpret_cast<uint2*>(g_xl)[i] = make_uint2(pack2(l0, l1), pack2(l2, l3));
    reinterpret_cast<uint2*>(g_x2)[i] = make_uint2(pack2(q0, q1), pack2(q2, q3));
}

// ---------------------------------------------------------------------------
// Main HMMA kernel. CTA = 128(M) x 64(N). 8 warps: 0-3 out, 4-7 var,
// each group 2x2 over the tile -> warp tile 64x32. 3-stage cp.async pipeline.
// ---------------------------------------------------------------------------
__global__ void __launch_bounds__(256, 1) bl_main(
    const float* __restrict__ bias_mu,
    const float* __restrict__ bias_ls,
    const float* __restrict__ eps_b,
    float* __restrict__ out,
    float* __restrict__ unc)
{
    extern __shared__ __align__(128) char dsm[];
    __shared__ float sbias[BN], sbs2[BN];

    const int tid = threadIdx.x;
    const int wid = tid >> 5;
    const int lid = tid & 31;
    const int bm  = blockIdx.y * BM;
    const int bn  = blockIdx.x * BN;

    if (tid < BN) {
        int n = bn + tid;
        float s = __expf(bias_ls[n]);
        sbias[tid] = bias_mu[n] + s * eps_b[n];
        sbs2[tid]  = s * s;
    }

    const __nv_bfloat16* __restrict__ Asrc[3] = {
        g_xh + (size_t)bm * IN_DIM, g_xl + (size_t)bm * IN_DIM,
        g_x2 + (size_t)bm * IN_DIM };
    const __nv_bfloat16* __restrict__ Bsrc[4] = {
        g_wh + (size_t)bn * IN_DIM, g_wl + (size_t)bn * IN_DIM,
        g_s2h + (size_t)bn * IN_DIM, g_s2l + (size_t)bn * IN_DIM };

    // --- stage loader: 2560 x 16B chunks, 10 per thread --------------------
    auto stage_load = [&](int slot, int kt) {
        char* st = dsm + slot * STAGE_BYTES;
#pragma unroll
        for (int t = 0; t < 3; ++t) {           // A tiles: 128x32 -> 512 chunks
#pragma unroll
            for (int it = 0; it < 2; ++it) {
                int id = it * 256 + tid;
                int row = id >> 2, c = id & 3;
                cp16(smem_u32(st + t * 8192 + swz(row, c)),
                     Asrc[t] + (size_t)row * IN_DIM + kt + c * 8);
            }
        }
#pragma unroll
        for (int t = 0; t < 4; ++t) {           // B tiles: 64x32 -> 256 chunks
            int row = tid >> 2, c = tid & 3;
            cp16(smem_u32(st + ST_WH + t * 4096 + swz(row, c)),
                 Bsrc[t] + (size_t)row * IN_DIM + kt + c * 8);
        }
    };

    stage_load(0, 0);       CP_COMMIT();
    stage_load(1, BK);      CP_COMMIT();

    float acc[4][4][4];
#pragma unroll
    for (int i = 0; i < 4; ++i)
#pragma unroll
        for (int j = 0; j < 4; ++j)
#pragma unroll
            for (int e = 0; e < 4; ++e) acc[i][j][e] = 0.f;

    const bool isVar = (wid >= 4);
    const int  w     = wid & 3;
    const int  wm    = (w >> 1) * 64;   // 0 / 64
    const int  wn    = (w & 1) * 32;    // 0 / 32
    const int  q     = lid >> 3;        // ldmatrix quadrant
    const int  r     = lid & 7;

    for (int c = 0; c < NCHUNK; ++c) {
        if (c + 2 < NCHUNK) stage_load((c + 2) % NSTAGE, (c + 2) * BK);
        CP_COMMIT();
        CP_WAIT2();
        __syncthreads();

        char* st = dsm + (c % NSTAGE) * STAGE_BYTES;
        const uint32_t a0b = smem_u32(st + (isVar ? ST_X2  : ST_XH));
        const uint32_t a1b = smem_u32(st + ST_XL);                 // out only
        const uint32_t b0b = smem_u32(st + (isVar ? ST_S2H : ST_WH));
        const uint32_t b1b = smem_u32(st + (isVar ? ST_S2L : ST_WL));

#pragma unroll
        for (int ks = 0; ks < 2; ++ks) {
            uint32_t a0[4][4], a1[4][4];
#pragma unroll
            for (int mt = 0; mt < 4; ++mt) {
                int row = wm + mt * 16 + ((q & 1) << 3) + r;
                int cc  = ks * 2 + (q >> 1);
                uint32_t off = swz(row, cc);
                ldsm_x4(a0[mt], a0b + off);
                if (!isVar) ldsm_x4(a1[mt], a1b + off);
            }
            uint32_t b0[2][4], b1[2][4];
#pragma unroll
            for (int p = 0; p < 2; ++p) {
                int row = wn + p * 16 + ((q >> 1) << 3) + r;
                int cc  = ks * 2 + (q & 1);
                uint32_t off = swz(row, cc);
                ldsm_x4(b0[p], b0b + off);
                ldsm_x4(b1[p], b1b + off);
            }
#pragma unroll
            for (int mt = 0; mt < 4; ++mt)
#pragma unroll
                for (int nt = 0; nt < 4; ++nt) {
                    const uint32_t* bh = &b0[nt >> 1][(nt & 1) * 2];
                    const uint32_t* bl = &b1[nt >> 1][(nt & 1) * 2];
                    mma_bf16(acc[mt][nt], a0[mt], bh);   // hh | x2*s2h
                    mma_bf16(acc[mt][nt], a0[mt], bl);   // hl | x2*s2l
                    if (!isVar)
                        mma_bf16(acc[mt][nt], a1[mt], bh);  // lh
                }
        }
        __syncthreads();   // readers done before next iter overwrites slot
    }

    // --- epilogue ----------------------------------------------------------
    const int g  = lid >> 2;
    const int tc = lid & 3;
    float* dst = isVar ? unc : out;
#pragma unroll
    for (int mt = 0; mt < 4; ++mt)
#pragma unroll
        for (int nt = 0; nt < 4; ++nt) {
            int m  = bm + wm + mt * 16 + g;
            int nl = wn + nt * 8 + tc * 2;
            size_t o0 = (size_t)m * OUT_DIM + bn + nl;
            const float* a = acc[mt][nt];
            float2 v0, v1;
            if (isVar) {
                v0 = make_float2(sqrtf(a[0] + sbs2[nl]), sqrtf(a[1] + sbs2[nl + 1]));
                v1 = make_float2(sqrtf(a[2] + sbs2[nl]), sqrtf(a[3] + sbs2[nl + 1]));
            } else {
                v0 = make_float2(a[0] + sbias[nl], a[1] + sbias[nl + 1]);
                v1 = make_float2(a[2] + sbias[nl], a[3] + sbias[nl + 1]);
            }
            *reinterpret_cast<float2*>(&dst[o0]) = v0;
            *reinterpret_cast<float2*>(&dst[o0 + 8 * OUT_DIM]) = v1;
        }
}

// ---------------------------------------------------------------------------
// kernel_launch — graph-capturable, allocation-free.
// Inputs: x, weight_mu, weight_log_sigma, bias_mu, bias_log_sigma, eps_w, eps_b
// Output: [output | uncertainty] fp32, each 4096x2048.
// ---------------------------------------------------------------------------
extern "C" void kernel_launch(void* const* d_in, const int* in_sizes, int n_in,
                              void* d_out, int out_size)
{
    const float* x   = (const float*)d_in[0];
    const float* wmu = (const float*)d_in[1];
    const float* wls = (const float*)d_in[2];
    const float* bmu = (const float*)d_in[3];
    const float* bls = (const float*)d_in[4];
    const float* ew  = (const float*)d_in[5];
    const float* eb  = (const float*)d_in[6];

    float* out = (float*)d_out;
    float* unc = out + (size_t)B_DIM * OUT_DIM;

    cudaFuncSetAttribute(bl_main, cudaFuncAttributeMaxDynamicSharedMemorySize,
                         SMEM_DYN);

    prep_w<<<(OUT_DIM * IN_DIM / 4) / 256, 256>>>(
        (const float4*)wmu, (const float4*)wls, (const float4*)ew);
    prep_x<<<(B_DIM * IN_DIM / 4) / 256, 256>>>((const float4*)x);

    dim3 grid(OUT_DIM / BN, B_DIM / BM);   // (32, 32) = 1024 CTAs
    bl_main<<<grid, 256, SMEM_DYN>>>(bmu, bls, eb, out, unc);

    (void)in_sizes; (void)n_in; (void)out_size;
}